// round 1
// baseline (speedup 1.0000x reference)
#include <cuda_runtime.h>
#include <cuda_bf16.h>
#include <cstdint>

#define NN   22528
#define EE   360448
#define FEA  60
#define HID  512
#define OUTD 4
#define MA   22
#define BGR  1024
#define CAT  572      // HID + FEA
#define FLAT 12584    // MA * CAT

// ---------------- device scratch (no allocations allowed) ----------------
__device__ int   g_flag;                       // 1 if edge_index is int64
__device__ float g_deg[NN];
__device__ float g_dis[NN];
__device__ int   g_row[EE];
__device__ int   g_col[EE];
__device__ float g_norm[EE];
__device__ float g_aggx[NN * FEA];             // aggregated x (conv1, pre-GEMM)
__device__ float g_h1[(size_t)NN * HID];       // conv1 output
__device__ float g_agg1[(size_t)NN * HID];     // aggregated h1 (conv2, pre-GEMM)
__device__ float g_xcat[(size_t)NN * CAT];     // [h2 | x] per node -> [1024, 12584] view
__device__ float g_t0[BGR * HID];
__device__ float g_t1[BGR * HID];

// ---------------- small kernels ----------------

// Detect int64 vs int32 edge_index layout. For int64 (values < 2^31, >=0),
// every odd 32-bit word of the buffer is 0. For int32 random values in
// [0, 22528), 64 consecutive zeros is impossible in practice.
__global__ void k_detect(const int* ei) {
    int f = 1;
    for (int i = 0; i < 64; i++) {
        if (ei[2 * i + 1] != 0) { f = 0; break; }
    }
    g_flag = f;
}

__global__ void k_init_deg() {
    int i = blockIdx.x * blockDim.x + threadIdx.x;
    if (i < NN) g_deg[i] = 1.0f;   // self-loop weight
}

__global__ void k_convert_deg(const void* ei, const float* __restrict__ ew) {
    int e = blockIdx.x * blockDim.x + threadIdx.x;
    if (e >= EE) return;
    int r, c;
    if (g_flag) {
        const long long* p = (const long long*)ei;
        r = (int)p[e]; c = (int)p[EE + e];
    } else {
        const int* p = (const int*)ei;
        r = p[e]; c = p[EE + e];
    }
    g_row[e] = r; g_col[e] = c;
    atomicAdd(&g_deg[c], ew[e]);
}

__global__ void k_dis() {
    int i = blockIdx.x * blockDim.x + threadIdx.x;
    if (i >= NN) return;
    float d = g_deg[i];
    g_dis[i] = (d > 0.f) ? rsqrtf(d) : 0.f;
}

__global__ void k_norm(const float* __restrict__ ew) {
    int e = blockIdx.x * blockDim.x + threadIdx.x;
    if (e >= EE) return;
    g_norm[e] = g_dis[g_row[e]] * ew[e] * g_dis[g_col[e]];
}

// aggx = self-loop contribution: dis[i]^2 * x[i]
__global__ void k_selfx(const float* __restrict__ x) {
    int t = blockIdx.x * blockDim.x + threadIdx.x;
    if (t >= NN * FEA) return;
    int n = t / FEA;
    float d = g_dis[n];
    g_aggx[t] = d * d * x[t];
}

// scatter x over edges (60 feats, padded lane space 64)
__global__ void k_scatter_x(const float* __restrict__ x) {
    int t = blockIdx.x * blockDim.x + threadIdx.x;
    int e = t >> 6, f = t & 63;
    if (e >= EE || f >= FEA) return;
    float nm = g_norm[e];
    atomicAdd(&g_aggx[(size_t)g_col[e] * FEA + f],
              x[(size_t)g_row[e] * FEA + f] * nm);
}

// agg1 = dis^2 * h1 (self loop), vectorized float4
__global__ void k_self1() {
    int t = blockIdx.x * blockDim.x + threadIdx.x;
    if (t >= NN * (HID / 4)) return;
    int n = t >> 7;   // / (HID/4)
    float d = g_dis[n];
    float s = d * d;
    float4 v = ((const float4*)g_h1)[t];
    v.x *= s; v.y *= s; v.z *= s; v.w *= s;
    ((float4*)g_agg1)[t] = v;
}

// scatter h1 over edges (512 feats = 128 float4 lanes per edge)
__global__ void k_scatter_h() {
    int t = blockIdx.x * blockDim.x + threadIdx.x;
    int e = t >> 7;
    if (e >= EE) return;
    int q = t & 127;
    float nm = g_norm[e];
    const float4* src = (const float4*)(g_h1 + (size_t)g_row[e] * HID);
    float4 v = src[q];
    float* dst = g_agg1 + (size_t)g_col[e] * HID + q * 4;
    atomicAdd(dst + 0, v.x * nm);
    atomicAdd(dst + 1, v.y * nm);
    atomicAdd(dst + 2, v.z * nm);
    atomicAdd(dst + 3, v.w * nm);
}

// copy raw x into xcat columns [512, 572)
__global__ void k_copyx(const float* __restrict__ x) {
    int t = blockIdx.x * blockDim.x + threadIdx.x;
    if (t >= NN * FEA) return;
    int n = t / FEA, f = t - n * FEA;
    g_xcat[(size_t)n * CAT + HID + f] = x[t];
}

// ---------------- SGEMM: C[M,N] = act(A[M,K] @ B[K,N] + bias) ----------------
// BM = TM*16, BN = 64, BK = 16, 256 threads (16x16), TNx4 register tile.
template <int TM>
__global__ void k_sgemm(const float* __restrict__ A, const float* __restrict__ B,
                        const float* __restrict__ bias, float* __restrict__ C,
                        int M, int N, int K, int lda, int ldb, int ldc, int act)
{
    constexpr int BM = TM * 16, BN = 64, BK = 16, TN = 4;
    __shared__ float As[BK][BM + 4];   // transposed: As[k][m]
    __shared__ float Bs[BK][BN + 4];
    const int tx = threadIdx.x, ty = threadIdx.y;
    const int tid = ty * 16 + tx;
    const int row0 = blockIdx.y * BM;
    const int col0 = blockIdx.x * BN;
    float acc[TM][TN] = {};

    for (int k0 = 0; k0 < K; k0 += BK) {
        #pragma unroll
        for (int j = 0; j < TM; j++) {
            int idx = tid + j * 256;
            int m = idx >> 4, kk = idx & 15;
            int gr = row0 + m, gk = k0 + kk;
            As[kk][m] = (gr < M && gk < K) ? A[(size_t)gr * lda + gk] : 0.f;
        }
        #pragma unroll
        for (int j = 0; j < 4; j++) {
            int idx = tid + j * 256;
            int kk = idx >> 6, n = idx & 63;
            int gk = k0 + kk, gn = col0 + n;
            Bs[kk][n] = (gk < K && gn < N) ? B[(size_t)gk * ldb + gn] : 0.f;
        }
        __syncthreads();
        #pragma unroll
        for (int kk = 0; kk < BK; kk++) {
            float ra[TM], rb[TN];
            #pragma unroll
            for (int i = 0; i < TM; i++) ra[i] = As[kk][ty * TM + i];
            #pragma unroll
            for (int j = 0; j < TN; j++) rb[j] = Bs[kk][tx * TN + j];
            #pragma unroll
            for (int i = 0; i < TM; i++)
                #pragma unroll
                for (int j = 0; j < TN; j++)
                    acc[i][j] += ra[i] * rb[j];
        }
        __syncthreads();
    }

    #pragma unroll
    for (int i = 0; i < TM; i++) {
        int r = row0 + ty * TM + i;
        if (r >= M) continue;
        #pragma unroll
        for (int j = 0; j < TN; j++) {
            int c = col0 + tx * TN + j;
            if (c >= N) continue;
            float v = acc[i][j] + bias[c];
            if (act) v = (v > 0.f) ? v : 0.01f * v;
            C[(size_t)r * ldc + c] = v;
        }
    }
}

// ---------------- final layer: logits + log_softmax ----------------
// one block (128 thr = 4 warps) per graph row; warp w computes output w
__global__ void k_out(const float* __restrict__ A, const float* __restrict__ Wo,
                      const float* __restrict__ bo, float* __restrict__ out)
{
    int b = blockIdx.x;
    int w = threadIdx.x >> 5, lane = threadIdx.x & 31;
    const float* a = A + (size_t)b * HID;
    float s = 0.f;
    for (int k = lane; k < HID; k += 32)
        s += a[k] * Wo[k * OUTD + w];
    #pragma unroll
    for (int o = 16; o > 0; o >>= 1) s += __shfl_xor_sync(0xFFFFFFFFu, s, o);
    __shared__ float sl[OUTD];
    if (lane == 0) sl[w] = s + bo[w];
    __syncthreads();
    if (threadIdx.x == 0) {
        float m = sl[0];
        #pragma unroll
        for (int o = 1; o < OUTD; o++) m = fmaxf(m, sl[o]);
        float sum = 0.f;
        #pragma unroll
        for (int o = 0; o < OUTD; o++) sum += expf(sl[o] - m);
        float l = logf(sum);
        #pragma unroll
        for (int o = 0; o < OUTD; o++) out[b * OUTD + o] = sl[o] - m - l;
    }
}

// ---------------- launch ----------------
static inline int cdiv(int a, int b) { return (a + b - 1) / b; }

extern "C" void kernel_launch(void* const* d_in, const int* in_sizes, int n_in,
                              void* d_out, int out_size)
{
    const float* x   = (const float*)d_in[0];
    const void*  ei  = d_in[1];
    const float* ew  = (const float*)d_in[2];
    const float* W1  = (const float*)d_in[3];
    const float* b1  = (const float*)d_in[4];
    const float* W2  = (const float*)d_in[5];
    const float* b2  = (const float*)d_in[6];
    const float* Wf0 = (const float*)d_in[7];
    const float* bf0 = (const float*)d_in[8];
    const float* Wf1 = (const float*)d_in[9];
    const float* bf1 = (const float*)d_in[10];
    const float* Wf2 = (const float*)d_in[11];
    const float* bf2 = (const float*)d_in[12];
    const float* Wo  = (const float*)d_in[13];
    const float* bo  = (const float*)d_in[14];
    float* out = (float*)d_out;

    float *aggx, *h1, *agg1, *xcat, *t0, *t1;
    cudaGetSymbolAddress((void**)&aggx, g_aggx);
    cudaGetSymbolAddress((void**)&h1,   g_h1);
    cudaGetSymbolAddress((void**)&agg1, g_agg1);
    cudaGetSymbolAddress((void**)&xcat, g_xcat);
    cudaGetSymbolAddress((void**)&t0,   g_t0);
    cudaGetSymbolAddress((void**)&t1,   g_t1);

    const int TPB = 256;

    // graph normalization
    k_detect<<<1, 1>>>((const int*)ei);
    k_init_deg<<<cdiv(NN, TPB), TPB>>>();
    k_convert_deg<<<cdiv(EE, TPB), TPB>>>(ei, ew);
    k_dis<<<cdiv(NN, TPB), TPB>>>();
    k_norm<<<cdiv(EE, TPB), TPB>>>(ew);

    // conv1: aggregate x first (60-dim), then GEMM -> leaky(.@W1 + b1)
    k_selfx<<<cdiv(NN * FEA, TPB), TPB>>>(x);
    k_scatter_x<<<cdiv(EE * 64, TPB), TPB>>>(x);
    {
        dim3 grid(cdiv(HID, 64), cdiv(NN, 128)), blk(16, 16);
        k_sgemm<8><<<grid, blk>>>(aggx, W1, b1, h1, NN, HID, FEA, FEA, HID, HID, 1);
    }

    // conv2: aggregate h1, then GEMM -> leaky(.@W2 + b2), written into xcat[:, :512]
    k_self1<<<cdiv(NN * (HID / 4), TPB), TPB>>>();
    k_scatter_h<<<cdiv(EE * 128, TPB), TPB>>>();
    {
        dim3 grid(cdiv(HID, 64), cdiv(NN, 128)), blk(16, 16);
        k_sgemm<8><<<grid, blk>>>(agg1, W2, b2, xcat, NN, HID, HID, HID, HID, CAT, 1);
    }
    k_copyx<<<cdiv(NN * FEA, TPB), TPB>>>(x);

    // MLP on [1024, 12584] view of xcat
    {
        dim3 blk(16, 16);
        dim3 g0(cdiv(HID, 64), cdiv(BGR, 64));
        k_sgemm<4><<<g0, blk>>>(xcat, Wf0, bf0, t0, BGR, HID, FLAT, FLAT, HID, HID, 1);
        k_sgemm<4><<<g0, blk>>>(t0, Wf1, bf1, t1, BGR, HID, HID, HID, HID, HID, 1);
        k_sgemm<4><<<g0, blk>>>(t1, Wf2, bf2, t0, BGR, HID, HID, HID, HID, HID, 1);
    }

    // output head + log_softmax
    k_out<<<BGR, 128>>>(t0, Wo, bo, out);
}

// round 2
// speedup vs baseline: 2.4392x; 2.4392x over previous
#include <cuda_runtime.h>
#include <cuda_bf16.h>
#include <cstdint>

#define NN   22528
#define EE   360448
#define FEA  60
#define HID  512
#define OUTD 4
#define MA   22
#define BGR  1024
#define CAT  572      // HID + FEA
#define FLAT 12584    // MA * CAT

// ---------------- device scratch ----------------
__device__ int   g_flag;
__device__ float g_deg[NN];
__device__ float g_dis[NN];
__device__ int   g_row[EE];
__device__ int   g_col[EE];
__device__ int   g_cnt[NN];
__device__ int   g_cur[NN];
__device__ int   g_off[NN + 1];
__device__ int   g_src[EE];          // CSR (by col): source node
__device__ float g_w[EE];            // CSR: edge norm weight
__device__ float g_W1p[64 * HID];    // zero-padded W1 (60->64 rows)
__device__ float g_aggx[NN * 64];    // aggregated x, padded to 64 cols
__device__ float g_h1[(size_t)NN * HID];
__device__ float g_agg1[(size_t)NN * HID];
__device__ float g_xcat[(size_t)NN * CAT];
__device__ float g_t0[BGR * HID];
__device__ float g_t1[BGR * HID];

// ---------------- f32x2 packed-FMA helpers ----------------
__device__ __forceinline__ unsigned long long pack2(float lo, float hi) {
    unsigned long long r;
    asm("mov.b64 %0, {%1, %2};" : "=l"(r) : "f"(lo), "f"(hi));
    return r;
}
__device__ __forceinline__ float2 unpack2(unsigned long long v) {
    float2 f;
    asm("mov.b64 {%0, %1}, %2;" : "=f"(f.x), "=f"(f.y) : "l"(v));
    return f;
}
__device__ __forceinline__ unsigned long long ffma2(unsigned long long a,
                                                    unsigned long long b,
                                                    unsigned long long c) {
    unsigned long long d;
    asm("fma.rn.f32x2 %0, %1, %2, %3;" : "=l"(d) : "l"(a), "l"(b), "l"(c));
    return d;
}
__device__ __forceinline__ float lrelu(float v) { return v > 0.f ? v : 0.01f * v; }

// ---------------- setup kernels ----------------
__global__ void k_detect(const int* ei) {
    int f = 1;
    for (int i = 0; i < 64; i++)
        if (ei[2 * i + 1] != 0) { f = 0; break; }
    g_flag = f;
}

__global__ void k_init() {
    int i = blockIdx.x * blockDim.x + threadIdx.x;
    if (i < NN) { g_deg[i] = 1.0f; g_cnt[i] = 0; g_cur[i] = 0; }
}

__global__ void k_edges(const void* ei, const float* __restrict__ ew) {
    int e = blockIdx.x * blockDim.x + threadIdx.x;
    if (e >= EE) return;
    int r, c;
    if (g_flag) {
        const long long* p = (const long long*)ei;
        r = (int)p[e]; c = (int)p[EE + e];
    } else {
        const int* p = (const int*)ei;
        r = p[e]; c = p[EE + e];
    }
    g_row[e] = r; g_col[e] = c;
    atomicAdd(&g_deg[c], ew[e]);
    atomicAdd(&g_cnt[c], 1);
}

__global__ void k_dis() {
    int i = blockIdx.x * blockDim.x + threadIdx.x;
    if (i >= NN) return;
    float d = g_deg[i];
    g_dis[i] = (d > 0.f) ? rsqrtf(d) : 0.f;
}

// single-block exclusive scan of g_cnt -> g_off  (22528 = 1024 * 22)
__global__ void k_scan() {
    __shared__ int sh[1024];
    int t = threadIdx.x;
    int base = t * 22;
    int local[22];
    int s = 0;
    #pragma unroll
    for (int i = 0; i < 22; i++) { local[i] = g_cnt[base + i]; s += local[i]; }
    sh[t] = s;
    __syncthreads();
    for (int off = 1; off < 1024; off <<= 1) {
        int v = (t >= off) ? sh[t - off] : 0;
        __syncthreads();
        sh[t] += v;
        __syncthreads();
    }
    int pre = (t == 0) ? 0 : sh[t - 1];
    #pragma unroll
    for (int i = 0; i < 22; i++) { g_off[base + i] = pre; pre += local[i]; }
    if (t == 0) g_off[NN] = EE;
}

__global__ void k_fill(const float* __restrict__ ew) {
    int e = blockIdx.x * blockDim.x + threadIdx.x;
    if (e >= EE) return;
    int r = g_row[e], c = g_col[e];
    int p = g_off[c] + atomicAdd(&g_cur[c], 1);
    g_src[p] = r;
    g_w[p] = g_dis[r] * ew[e] * g_dis[c];
}

// ---------------- CSR gathers (no atomics) ----------------
// conv1 aggregation: aggx[n, 0:60] = dis[n]^2*x[n] + sum_e w*x[src]; cols 60..63 = 0
__global__ void k_gather1(const float* __restrict__ x) {
    int n = blockIdx.x;
    int f = threadIdx.x;               // 64 threads
    float d = g_dis[n];
    float acc = 0.f;
    if (f < FEA) acc = d * d * x[(size_t)n * FEA + f];
    int s = g_off[n], e = g_off[n + 1];
    for (int p = s; p < e; p++) {
        int src = g_src[p];
        float w = g_w[p];
        if (f < FEA) acc += x[(size_t)src * FEA + f] * w;
    }
    g_aggx[(size_t)n * 64 + f] = (f < FEA) ? acc : 0.f;
}

// conv2 aggregation: agg1[n] = dis[n]^2*h1[n] + sum_e w*h1[src]  (512 feats, float2/thread)
__global__ void k_gather2() {
    int n = blockIdx.x;
    int f2 = threadIdx.x;              // 256 threads -> float2 each
    float d = g_dis[n];
    float s2 = d * d;
    float2 acc = ((const float2*)(g_h1 + (size_t)n * HID))[f2];
    acc.x *= s2; acc.y *= s2;
    int s = g_off[n], e = g_off[n + 1];
    for (int p = s; p < e; p++) {
        int src = g_src[p];
        float w = g_w[p];
        float2 v = ((const float2*)(g_h1 + (size_t)src * HID))[f2];
        acc.x += v.x * w;
        acc.y += v.y * w;
    }
    ((float2*)(g_agg1 + (size_t)n * HID))[f2] = acc;
}

__global__ void k_padW1(const float* __restrict__ W1) {
    int t = blockIdx.x * blockDim.x + threadIdx.x;
    if (t >= 64 * HID) return;
    int r = t >> 9;
    g_W1p[t] = (r < FEA) ? W1[t - ((r - FEA) << 9) - (FEA << 9)] : 0.f;
}
// note: simpler correct index below
__global__ void k_padW1b(const float* __restrict__ W1) {
    int t = blockIdx.x * blockDim.x + threadIdx.x;
    if (t >= 64 * HID) return;
    int r = t >> 9, c = t & 511;
    g_W1p[t] = (r < FEA) ? W1[r * HID + c] : 0.f;
}

__global__ void k_copyx(const float* __restrict__ x) {
    int t = blockIdx.x * blockDim.x + threadIdx.x;
    if (t >= NN * FEA) return;
    int n = t / FEA, f = t - n * FEA;
    g_xcat[(size_t)n * CAT + HID + f] = x[t];
}

// ---------------- big GEMM: 128x128 tile, BK=16, f32x2, leaky+bias ----------------
// Requires M%128==0, N%128==0 (grid covers), K%16==0, ldb=512. No bounds checks.
__global__ void __launch_bounds__(256, 2)
k_gemm_big(const float* __restrict__ A, const float* __restrict__ B,
           const float* __restrict__ bias, float* __restrict__ C,
           int K, int lda, int ldc)
{
    const int BK = 16;
    __shared__ float As[BK][132];
    __shared__ float Bs[BK][132];
    int tid = threadIdx.x;
    int tx = tid & 15, ty = tid >> 4;
    int row0 = blockIdx.y * 128, col0 = blockIdx.x * 128;
    unsigned long long acc[8][4];
    #pragma unroll
    for (int i = 0; i < 8; i++)
        #pragma unroll
        for (int j = 0; j < 4; j++) acc[i][j] = 0ull;

    for (int k0 = 0; k0 < K; k0 += BK) {
        #pragma unroll
        for (int j = 0; j < 2; j++) {
            int idx = tid + j * 256;
            int r = idx >> 2;
            int kk = (idx & 3) * 4;
            float4 v = *(const float4*)&A[(size_t)(row0 + r) * lda + k0 + kk];
            As[kk + 0][r] = v.x; As[kk + 1][r] = v.y;
            As[kk + 2][r] = v.z; As[kk + 3][r] = v.w;
        }
        #pragma unroll
        for (int j = 0; j < 2; j++) {
            int idx = tid + j * 256;
            int kk = idx >> 5;
            int n4 = (idx & 31) * 4;
            *(float4*)&Bs[kk][n4] = *(const float4*)&B[(size_t)(k0 + kk) * HID + col0 + n4];
        }
        __syncthreads();
        #pragma unroll
        for (int kk = 0; kk < BK; kk++) {
            float4 a0 = *(const float4*)&As[kk][ty * 8];
            float4 a1 = *(const float4*)&As[kk][ty * 8 + 4];
            float4 b0 = *(const float4*)&Bs[kk][tx * 8];
            float4 b1 = *(const float4*)&Bs[kk][tx * 8 + 4];
            unsigned long long bb[4] = { pack2(b0.x, b0.y), pack2(b0.z, b0.w),
                                         pack2(b1.x, b1.y), pack2(b1.z, b1.w) };
            float ar[8] = {a0.x, a0.y, a0.z, a0.w, a1.x, a1.y, a1.z, a1.w};
            #pragma unroll
            for (int i = 0; i < 8; i++) {
                unsigned long long aa = pack2(ar[i], ar[i]);
                #pragma unroll
                for (int j = 0; j < 4; j++) acc[i][j] = ffma2(aa, bb[j], acc[i][j]);
            }
        }
        __syncthreads();
    }

    float bs[8];
    #pragma unroll
    for (int j = 0; j < 8; j++) bs[j] = bias[col0 + tx * 8 + j];
    #pragma unroll
    for (int i = 0; i < 8; i++) {
        int r = row0 + ty * 8 + i;
        float* crow = C + (size_t)r * ldc + col0 + tx * 8;
        float2 v0 = unpack2(acc[i][0]), v1 = unpack2(acc[i][1]);
        float2 v2 = unpack2(acc[i][2]), v3 = unpack2(acc[i][3]);
        float4 o0 = { lrelu(v0.x + bs[0]), lrelu(v0.y + bs[1]),
                      lrelu(v1.x + bs[2]), lrelu(v1.y + bs[3]) };
        float4 o1 = { lrelu(v2.x + bs[4]), lrelu(v2.y + bs[5]),
                      lrelu(v3.x + bs[6]), lrelu(v3.y + bs[7]) };
        *(float4*)&crow[0] = o0;
        *(float4*)&crow[4] = o1;
    }
}

// ---------------- small GEMM: 64x64 tile, BK=16, split-K capable ----------------
// MODE 0: direct store with bias + leaky (single z). MODE 1: atomicAdd partials.
// ldb = 512. K chunk boundaries multiple of 4 (alignment-safe float4 loads).
template <int MODE>
__global__ void __launch_bounds__(256, 4)
k_gemm_small(const float* __restrict__ A, const float* __restrict__ B,
             const float* __restrict__ bias, float* __restrict__ C,
             int K, int lda, int chunk)
{
    const int BK = 16;
    __shared__ float As[BK][68];
    __shared__ float Bs[BK][68];
    int tid = threadIdx.x;
    int tx = tid & 15, ty = tid >> 4;
    int row0 = blockIdx.y * 64, col0 = blockIdx.x * 64;
    int kb = blockIdx.z * chunk;
    int ke = min(K, kb + chunk);
    unsigned long long acc[4][2];
    #pragma unroll
    for (int i = 0; i < 4; i++) { acc[i][0] = 0ull; acc[i][1] = 0ull; }

    for (int k0 = kb; k0 < ke; k0 += BK) {
        {
            int r = tid >> 2;
            int kk = (tid & 3) * 4;
            int gk = k0 + kk;
            float4 v = {0.f, 0.f, 0.f, 0.f};
            if (gk < ke) v = *(const float4*)&A[(size_t)(row0 + r) * lda + gk];
            As[kk + 0][r] = v.x; As[kk + 1][r] = v.y;
            As[kk + 2][r] = v.z; As[kk + 3][r] = v.w;
        }
        {
            int kk = tid >> 4;
            int n4 = (tid & 15) * 4;
            int gk = k0 + kk;
            float4 v = {0.f, 0.f, 0.f, 0.f};
            if (gk < ke) v = *(const float4*)&B[(size_t)gk * HID + col0 + n4];
            *(float4*)&Bs[kk][n4] = v;
        }
        __syncthreads();
        #pragma unroll
        for (int kk = 0; kk < BK; kk++) {
            float4 a = *(const float4*)&As[kk][ty * 4];
            float4 b = *(const float4*)&Bs[kk][tx * 4];
            unsigned long long bb[2] = { pack2(b.x, b.y), pack2(b.z, b.w) };
            float ar[4] = {a.x, a.y, a.z, a.w};
            #pragma unroll
            for (int i = 0; i < 4; i++) {
                unsigned long long aa = pack2(ar[i], ar[i]);
                acc[i][0] = ffma2(aa, bb[0], acc[i][0]);
                acc[i][1] = ffma2(aa, bb[1], acc[i][1]);
            }
        }
        __syncthreads();
    }

    if (MODE == 1) {
        #pragma unroll
        for (int i = 0; i < 4; i++) {
            int r = row0 + ty * 4 + i;
            float* crow = C + (size_t)r * HID + col0 + tx * 4;
            float2 v0 = unpack2(acc[i][0]), v1 = unpack2(acc[i][1]);
            atomicAdd(&crow[0], v0.x);
            atomicAdd(&crow[1], v0.y);
            atomicAdd(&crow[2], v1.x);
            atomicAdd(&crow[3], v1.y);
        }
    } else {
        float bs[4];
        #pragma unroll
        for (int j = 0; j < 4; j++) bs[j] = bias[col0 + tx * 4 + j];
        #pragma unroll
        for (int i = 0; i < 4; i++) {
            int r = row0 + ty * 4 + i;
            float2 v0 = unpack2(acc[i][0]), v1 = unpack2(acc[i][1]);
            float4 o = { lrelu(v0.x + bs[0]), lrelu(v0.y + bs[1]),
                         lrelu(v1.x + bs[2]), lrelu(v1.y + bs[3]) };
            *(float4*)&C[(size_t)r * HID + col0 + tx * 4] = o;
        }
    }
}

__global__ void k_zero_t0() {
    int t = blockIdx.x * blockDim.x + threadIdx.x;
    if (t < BGR * HID) g_t0[t] = 0.f;
}

__global__ void k_biasleaky(const float* __restrict__ bias) {
    int t = blockIdx.x * blockDim.x + threadIdx.x;
    if (t >= BGR * HID) return;
    int c = t & 511;
    g_t0[t] = lrelu(g_t0[t] + bias[c]);
}

// ---------------- final layer: logits + log_softmax ----------------
__global__ void k_out(const float* __restrict__ A, const float* __restrict__ Wo,
                      const float* __restrict__ bo, float* __restrict__ out)
{
    int b = blockIdx.x;
    int w = threadIdx.x >> 5, lane = threadIdx.x & 31;
    const float* a = A + (size_t)b * HID;
    float s = 0.f;
    for (int k = lane; k < HID; k += 32)
        s += a[k] * Wo[k * OUTD + w];
    #pragma unroll
    for (int o = 16; o > 0; o >>= 1) s += __shfl_xor_sync(0xFFFFFFFFu, s, o);
    __shared__ float sl[OUTD];
    if (lane == 0) sl[w] = s + bo[w];
    __syncthreads();
    if (threadIdx.x == 0) {
        float m = sl[0];
        #pragma unroll
        for (int o = 1; o < OUTD; o++) m = fmaxf(m, sl[o]);
        float sum = 0.f;
        #pragma unroll
        for (int o = 0; o < OUTD; o++) sum += expf(sl[o] - m);
        float l = logf(sum);
        #pragma unroll
        for (int o = 0; o < OUTD; o++) out[b * OUTD + o] = sl[o] - m - l;
    }
}

// ---------------- launch ----------------
static inline int cdiv(int a, int b) { return (a + b - 1) / b; }

extern "C" void kernel_launch(void* const* d_in, const int* in_sizes, int n_in,
                              void* d_out, int out_size)
{
    const float* x   = (const float*)d_in[0];
    const void*  ei  = d_in[1];
    const float* ew  = (const float*)d_in[2];
    const float* W1  = (const float*)d_in[3];
    const float* b1  = (const float*)d_in[4];
    const float* W2  = (const float*)d_in[5];
    const float* b2  = (const float*)d_in[6];
    const float* Wf0 = (const float*)d_in[7];
    const float* bf0 = (const float*)d_in[8];
    const float* Wf1 = (const float*)d_in[9];
    const float* bf1 = (const float*)d_in[10];
    const float* Wf2 = (const float*)d_in[11];
    const float* bf2 = (const float*)d_in[12];
    const float* Wo  = (const float*)d_in[13];
    const float* bo  = (const float*)d_in[14];
    float* out = (float*)d_out;

    float *aggx, *h1, *agg1, *xcat, *t0, *t1, *W1p;
    cudaGetSymbolAddress((void**)&aggx, g_aggx);
    cudaGetSymbolAddress((void**)&h1,   g_h1);
    cudaGetSymbolAddress((void**)&agg1, g_agg1);
    cudaGetSymbolAddress((void**)&xcat, g_xcat);
    cudaGetSymbolAddress((void**)&t0,   g_t0);
    cudaGetSymbolAddress((void**)&t1,   g_t1);
    cudaGetSymbolAddress((void**)&W1p,  g_W1p);

    const int TPB = 256;

    // graph normalization + CSR build
    k_detect<<<1, 1>>>((const int*)ei);
    k_init<<<cdiv(NN, TPB), TPB>>>();
    k_edges<<<cdiv(EE, TPB), TPB>>>(ei, ew);
    k_dis<<<cdiv(NN, TPB), TPB>>>();
    k_scan<<<1, 1024>>>();
    k_fill<<<cdiv(EE, TPB), TPB>>>(ew);
    k_padW1b<<<cdiv(64 * HID, TPB), TPB>>>(W1);

    // conv1: CSR gather (60-dim) then GEMM
    k_gather1<<<NN, 64>>>(x);
    {
        dim3 grid(HID / 128, NN / 128);
        k_gemm_big<<<grid, 256>>>(aggx, W1p, b1, h1, 64, 64, HID);
    }

    // conv2: CSR gather (512-dim) then GEMM into xcat[:, :512]
    k_gather2<<<NN, 256>>>();
    {
        dim3 grid(HID / 128, NN / 128);
        k_gemm_big<<<grid, 256>>>(agg1, W2, b2, xcat, HID, HID, CAT);
    }
    k_copyx<<<cdiv(NN * FEA, TPB), TPB>>>(x);

    // MLP: f0 with split-K (chunk 1576, 8 chunks), then f1, f2
    k_zero_t0<<<cdiv(BGR * HID, TPB), TPB>>>();
    {
        dim3 g0(HID / 64, BGR / 64, 8);
        k_gemm_small<1><<<g0, 256>>>(xcat, Wf0, nullptr, t0, FLAT, FLAT, 1576);
    }
    k_biasleaky<<<cdiv(BGR * HID, TPB), TPB>>>(bf0);
    {
        dim3 g1(HID / 64, BGR / 64, 1);
        k_gemm_small<0><<<g1, 256>>>(t0, Wf1, bf1, t1, HID, HID, HID);
        k_gemm_small<0><<<g1, 256>>>(t1, Wf2, bf2, t0, HID, HID, HID);
    }

    // output head + log_softmax
    k_out<<<BGR, 128>>>(t0, Wo, bo, out);
}

// round 4
// speedup vs baseline: 4.5375x; 1.8603x over previous
#include <cuda_runtime.h>
#include <cuda_bf16.h>
#include <cstdint>

#define NN   22528
#define EE   360448
#define FEA  60
#define HID  512
#define OUTD 4
#define MA   22
#define BGR  1024
#define CAT  572
#define FLAT 12584
#define KP0  12608        // FLAT padded to 64
#define NCH0 197          // KP0/64 chunks for f0

// ---------------- device scratch ----------------
__device__ int   g_flag;
__device__ float g_deg[NN];
__device__ float g_dis[NN];
__device__ int   g_row[EE];
__device__ int   g_col[EE];
__device__ int   g_cnt[NN];
__device__ int   g_cur[NN];
__device__ int   g_off[NN + 1];
__device__ int   g_src[EE];
__device__ float g_w[EE];

__device__ __align__(16) __nv_bfloat16 g_aggx_h[(size_t)NN * 64];
__device__ __align__(16) __nv_bfloat16 g_aggx_l[(size_t)NN * 64];
__device__ __align__(16) __nv_bfloat16 g_W1t_h[512 * 64];
__device__ __align__(16) __nv_bfloat16 g_W1t_l[512 * 64];
__device__ __align__(16) float         g_h1[(size_t)NN * HID];
__device__ __align__(16) __nv_bfloat16 g_W2t_h[512 * 512];
__device__ __align__(16) __nv_bfloat16 g_W2t_l[512 * 512];
__device__ __align__(16) __nv_bfloat16 g_agg1_h[(size_t)NN * HID];
__device__ __align__(16) __nv_bfloat16 g_agg1_l[(size_t)NN * HID];
__device__ __align__(16) __nv_bfloat16 g_xcat_h[(size_t)BGR * KP0];
__device__ __align__(16) __nv_bfloat16 g_xcat_l[(size_t)BGR * KP0];
__device__ __align__(16) __nv_bfloat16 g_Wf0t_h[(size_t)512 * KP0];
__device__ __align__(16) __nv_bfloat16 g_Wf0t_l[(size_t)512 * KP0];
__device__ __align__(16) float         g_t0f[BGR * HID];
__device__ __align__(16) __nv_bfloat16 g_t0_h[BGR * HID];
__device__ __align__(16) __nv_bfloat16 g_t0_l[BGR * HID];
__device__ __align__(16) __nv_bfloat16 g_Wf1t_h[512 * 512];
__device__ __align__(16) __nv_bfloat16 g_Wf1t_l[512 * 512];
__device__ __align__(16) __nv_bfloat16 g_t1_h[BGR * HID];
__device__ __align__(16) __nv_bfloat16 g_t1_l[BGR * HID];
__device__ __align__(16) __nv_bfloat16 g_Wf2t_h[512 * 512];
__device__ __align__(16) __nv_bfloat16 g_Wf2t_l[512 * 512];
__device__ __align__(16) float         g_t2[BGR * HID];

// ---------------- helpers ----------------
__device__ __forceinline__ uint32_t smem_u32(const void* p) {
    uint32_t a;
    asm("{ .reg .u64 t; cvta.to.shared.u64 t, %1; cvt.u32.u64 %0, t; }" : "=r"(a) : "l"(p));
    return a;
}
__device__ __forceinline__ void ldsm4(uint32_t* r, uint32_t addr) {
    asm volatile("ldmatrix.sync.aligned.m8n8.x4.shared.b16 {%0,%1,%2,%3}, [%4];"
        : "=r"(r[0]), "=r"(r[1]), "=r"(r[2]), "=r"(r[3]) : "r"(addr));
}
__device__ __forceinline__ void mma16816(float* d, const uint32_t* a, uint32_t b0, uint32_t b1) {
    asm volatile("mma.sync.aligned.m16n8k16.row.col.f32.bf16.bf16.f32 "
        "{%0,%1,%2,%3}, {%4,%5,%6,%7}, {%8,%9}, {%0,%1,%2,%3};"
        : "+f"(d[0]), "+f"(d[1]), "+f"(d[2]), "+f"(d[3])
        : "r"(a[0]), "r"(a[1]), "r"(a[2]), "r"(a[3]), "r"(b0), "r"(b1));
}
#define CP16(d, s)   asm volatile("cp.async.cg.shared.global [%0], [%1], 16;" :: "r"(d), "l"(s))
#define CP_COMMIT()  asm volatile("cp.async.commit_group;" ::: "memory")
#define CP_WAIT0()   asm volatile("cp.async.wait_group 0;" ::: "memory")
#define CP_WAIT1()   asm volatile("cp.async.wait_group 1;" ::: "memory")

__device__ __forceinline__ float lrelu(float v) { return v > 0.f ? v : 0.01f * v; }
__device__ __forceinline__ void split_bf16(float v, __nv_bfloat16& h, __nv_bfloat16& l) {
    h = __float2bfloat16(v);
    l = __float2bfloat16(v - __bfloat162float(h));
}

// ---------------- setup kernels ----------------
__global__ void k_detect(const int* ei) {
    int f = 1;
    for (int i = 0; i < 64; i++)
        if (ei[2 * i + 1] != 0) { f = 0; break; }
    g_flag = f;
}
__global__ void k_init() {
    int i = blockIdx.x * blockDim.x + threadIdx.x;
    if (i < NN) { g_deg[i] = 1.0f; g_cnt[i] = 0; g_cur[i] = 0; }
}
__global__ void k_edges(const void* ei, const float* __restrict__ ew) {
    int e = blockIdx.x * blockDim.x + threadIdx.x;
    if (e >= EE) return;
    int r, c;
    if (g_flag) {
        const long long* p = (const long long*)ei;
        r = (int)p[e]; c = (int)p[EE + e];
    } else {
        const int* p = (const int*)ei;
        r = p[e]; c = p[EE + e];
    }
    g_row[e] = r; g_col[e] = c;
    atomicAdd(&g_deg[c], ew[e]);
    atomicAdd(&g_cnt[c], 1);
}
__global__ void k_dis() {
    int i = blockIdx.x * blockDim.x + threadIdx.x;
    if (i >= NN) return;
    float d = g_deg[i];
    g_dis[i] = (d > 0.f) ? rsqrtf(d) : 0.f;
}
__global__ void k_scan() {
    __shared__ int sh[1024];
    int t = threadIdx.x;
    int base = t * 22;
    int local[22];
    int s = 0;
    #pragma unroll
    for (int i = 0; i < 22; i++) { local[i] = g_cnt[base + i]; s += local[i]; }
    sh[t] = s;
    __syncthreads();
    for (int off = 1; off < 1024; off <<= 1) {
        int v = (t >= off) ? sh[t - off] : 0;
        __syncthreads();
        sh[t] += v;
        __syncthreads();
    }
    int pre = (t == 0) ? 0 : sh[t - 1];
    #pragma unroll
    for (int i = 0; i < 22; i++) { g_off[base + i] = pre; pre += local[i]; }
    if (t == 0) g_off[NN] = EE;
}
__global__ void k_fill(const float* __restrict__ ew) {
    int e = blockIdx.x * blockDim.x + threadIdx.x;
    if (e >= EE) return;
    int r = g_row[e], c = g_col[e];
    int p = g_off[c] + atomicAdd(&g_cur[c], 1);
    g_src[p] = r;
    g_w[p] = g_dis[r] * ew[e] * g_dis[c];
}

// ---------------- CSR gathers ----------------
__global__ void k_gather1(const float* __restrict__ x) {
    int n = blockIdx.x;
    int f = threadIdx.x;               // 64
    float d = g_dis[n];
    float acc = 0.f;
    if (f < FEA) acc = d * d * x[(size_t)n * FEA + f];
    int s = g_off[n], e = g_off[n + 1];
    for (int p = s; p < e; p++) {
        int src = g_src[p];
        float w = g_w[p];
        if (f < FEA) acc += x[(size_t)src * FEA + f] * w;
    }
    if (f >= FEA) acc = 0.f;
    __nv_bfloat16 h, l;
    split_bf16(acc, h, l);
    g_aggx_h[(size_t)n * 64 + f] = h;
    g_aggx_l[(size_t)n * 64 + f] = l;
}

__global__ void k_gather2() {
    int n = blockIdx.x;
    int f2 = threadIdx.x;              // 256 -> float2 each
    float d = g_dis[n];
    float s2 = d * d;
    float2 acc = ((const float2*)(g_h1 + (size_t)n * HID))[f2];
    acc.x *= s2; acc.y *= s2;
    int s = g_off[n], e = g_off[n + 1];
    for (int p = s; p < e; p++) {
        int src = g_src[p];
        float w = g_w[p];
        float2 v = ((const float2*)(g_h1 + (size_t)src * HID))[f2];
        acc.x += v.x * w;
        acc.y += v.y * w;
    }
    __nv_bfloat16 hx, lx, hy, ly;
    split_bf16(acc.x, hx, lx);
    split_bf16(acc.y, hy, ly);
    ((__nv_bfloat162*)(g_agg1_h + (size_t)n * HID))[f2] = __nv_bfloat162(hx, hy);
    ((__nv_bfloat162*)(g_agg1_l + (size_t)n * HID))[f2] = __nv_bfloat162(lx, ly);
}

// ---------------- weight transpose + split: W[K,512] -> Wt[512,Kpad] ----------------
__global__ void k_wtrans(const float* __restrict__ W, int K, int Kpad,
                         __nv_bfloat16* __restrict__ oh, __nv_bfloat16* __restrict__ ol) {
    __shared__ float tile[32][33];
    int kb = blockIdx.x * 32, nb = blockIdx.y * 32;
    int tx = threadIdx.x, ty = threadIdx.y;   // 32 x 8
    #pragma unroll
    for (int i = 0; i < 4; i++) {
        int row = kb + ty + i * 8;
        tile[ty + i * 8][tx] = (row < K) ? W[(size_t)row * 512 + nb + tx] : 0.f;
    }
    __syncthreads();
    #pragma unroll
    for (int i = 0; i < 4; i++) {
        int n = nb + ty + i * 8;
        int k = kb + tx;
        float v = tile[tx][ty + i * 8];
        __nv_bfloat16 h, l;
        split_bf16(v, h, l);
        oh[(size_t)n * Kpad + k] = h;
        ol[(size_t)n * Kpad + k] = l;
    }
}

__global__ void k_copyx(const float* __restrict__ x) {
    int t = blockIdx.x * blockDim.x + threadIdx.x;
    if (t >= NN * FEA) return;
    int n = t / FEA, f = t - n * FEA;
    int b = n / MA, j = n - b * MA;
    size_t o = (size_t)b * KP0 + j * CAT + HID + f;
    __nv_bfloat16 h, l;
    split_bf16(x[t], h, l);
    g_xcat_h[o] = h;
    g_xcat_l[o] = l;
}
__global__ void k_padxcat() {
    int t = blockIdx.x * blockDim.x + threadIdx.x;
    if (t >= BGR * 24) return;
    int b = t / 24, f = t - b * 24;
    size_t o = (size_t)b * KP0 + FLAT + f;
    g_xcat_h[o] = __float2bfloat16(0.f);
    g_xcat_l[o] = __float2bfloat16(0.f);
}
__global__ void k_zero_t0f() {
    int t = blockIdx.x * blockDim.x + threadIdx.x;
    if (t < BGR * HID) g_t0f[t] = 0.f;
}
__global__ void k_fin_t0(const float* __restrict__ bias) {
    int t = blockIdx.x * blockDim.x + threadIdx.x;
    if (t >= BGR * HID) return;
    int c = t & 511;
    float v = lrelu(g_t0f[t] + bias[c]);
    __nv_bfloat16 h, l;
    split_bf16(v, h, l);
    g_t0_h[t] = h;
    g_t0_l[t] = l;
}

// ================= mma.sync split-bf16 GEMM =================
// C[M, 512] = A[M, K] @ Wt[512, K]^T  with ~fp32 accuracy (hi*hi + hi*lo + lo*hi).
// CTA tile 128x128, 8 warps each 64x32. BK = 64. cp.async double buffer.
// Smem rows padded to 144 B (36 words) -> conflict-free ldmatrix & fills.
// EPI: 0 fp32+bias+lrelu, 1 bf16 hi/lo+bias+lrelu, 2 xcat-scatter, 3 atomicAdd raw.
#define OFF_AL 18432u
#define OFF_BH 36864u
#define OFF_BL 55296u
#define BUFSZ  73728u

template <int EPI>
__global__ void __launch_bounds__(256, 1)
k_mma_gemm(const __nv_bfloat16* __restrict__ Ah, const __nv_bfloat16* __restrict__ Al, int lda,
           const __nv_bfloat16* __restrict__ Bh, const __nv_bfloat16* __restrict__ Bl, int ldb,
           const float* __restrict__ bias,
           float* __restrict__ Cf, __nv_bfloat16* __restrict__ Ch, __nv_bfloat16* __restrict__ Cl,
           int ldc, int nch, int cper)
{
    extern __shared__ char smx[];
    const uint32_t smb = smem_u32(smx);
    const int tid = threadIdx.x;
    const int wid = tid >> 5, lane = tid & 31;
    const int wm = wid & 1, wn = wid >> 1;
    const int row0 = blockIdx.y * 128, col0 = blockIdx.x * 128;
    const int c0 = blockIdx.z * cper;
    const int nc = min(nch, c0 + cper) - c0;

    const __nv_bfloat16* pAh = Ah + (size_t)row0 * lda;
    const __nv_bfloat16* pAl = Al + (size_t)row0 * lda;
    const __nv_bfloat16* pBh = Bh + (size_t)col0 * ldb;
    const __nv_bfloat16* pBl = Bl + (size_t)col0 * ldb;

    auto fill = [&](int b, int c) {
        const int kb = c * 64;
        uint32_t base = smb + b * BUFSZ;
        #pragma unroll
        for (int i = 0; i < 4; i++) {
            int idx = i * 256 + tid;
            int row = idx >> 3, seg = idx & 7;
            uint32_t d = base + (uint32_t)(row * 144 + seg * 16);
            size_t sa = (size_t)row * lda + kb + seg * 8;
            size_t sb = (size_t)row * ldb + kb + seg * 8;
            CP16(d,          pAh + sa);
            CP16(d + OFF_AL, pAl + sa);
            CP16(d + OFF_BH, pBh + sb);
            CP16(d + OFF_BL, pBl + sb);
        }
    };

    float acc[4][4][4];
    #pragma unroll
    for (int i = 0; i < 4; i++)
        #pragma unroll
        for (int j = 0; j < 4; j++)
            #pragma unroll
            for (int q = 0; q < 4; q++) acc[i][j][q] = 0.f;

    const int g2 = lane >> 3, rr = lane & 7;
    const uint32_t aoff = (uint32_t)((wm * 64 + (g2 & 1) * 8 + rr) * 144 + (g2 >> 1) * 16);
    const uint32_t boff = (uint32_t)((wn * 32 + (g2 >> 1) * 8 + rr) * 144 + (g2 & 1) * 16);

    fill(0, c0);
    CP_COMMIT();

    for (int ci = 0; ci < nc; ci++) {
        if (ci + 1 < nc) { fill((ci + 1) & 1, c0 + ci + 1); CP_COMMIT(); CP_WAIT1(); }
        else             { CP_WAIT0(); }
        __syncthreads();
        uint32_t base = smb + (ci & 1) * BUFSZ;
        #pragma unroll
        for (int k16 = 0; k16 < 4; k16++) {
            uint32_t Af[4][4], Lf[4][4], Bf[2][4], Mf[2][4];
            #pragma unroll
            for (int mt = 0; mt < 4; mt++) {
                ldsm4(Af[mt], base + aoff + mt * 2304 + k16 * 32);
                ldsm4(Lf[mt], base + OFF_AL + aoff + mt * 2304 + k16 * 32);
            }
            #pragma unroll
            for (int nt2 = 0; nt2 < 2; nt2++) {
                ldsm4(Bf[nt2], base + OFF_BH + boff + nt2 * 2304 + k16 * 32);
                ldsm4(Mf[nt2], base + OFF_BL + boff + nt2 * 2304 + k16 * 32);
            }
            #pragma unroll
            for (int mt = 0; mt < 4; mt++)
                #pragma unroll
                for (int nt = 0; nt < 4; nt++) {
                    uint32_t bh0 = Bf[nt >> 1][(nt & 1) * 2], bh1 = Bf[nt >> 1][(nt & 1) * 2 + 1];
                    uint32_t bl0 = Mf[nt >> 1][(nt & 1) * 2], bl1 = Mf[nt >> 1][(nt & 1) * 2 + 1];
                    mma16816(acc[mt][nt], Af[mt], bh0, bh1);
                    mma16816(acc[mt][nt], Af[mt], bl0, bl1);
                    mma16816(acc[mt][nt], Lf[mt], bh0, bh1);
                }
        }
        __syncthreads();
    }

    // ---------------- epilogue ----------------
    const int g = lane >> 2, t = lane & 3;
    #pragma unroll
    for (int mt = 0; mt < 4; mt++) {
        const int ra = row0 + wm * 64 + mt * 16 + g;
        const int rb = ra + 8;
        size_t oa = 0, ob = 0;
        if (EPI == 2) {
            int bg = ra / MA, j = ra - bg * MA;
            oa = (size_t)bg * KP0 + (size_t)j * CAT;
            bg = rb / MA; j = rb - bg * MA;
            ob = (size_t)bg * KP0 + (size_t)j * CAT;
        }
        #pragma unroll
        for (int nt = 0; nt < 4; nt++) {
            const int c = col0 + wn * 32 + nt * 8 + t * 2;
            float* d = acc[mt][nt];
            if (EPI == 3) {
                atomicAdd(&Cf[(size_t)ra * ldc + c],     d[0]);
                atomicAdd(&Cf[(size_t)ra * ldc + c + 1], d[1]);
                atomicAdd(&Cf[(size_t)rb * ldc + c],     d[2]);
                atomicAdd(&Cf[(size_t)rb * ldc + c + 1], d[3]);
            } else {
                float2 bv = *(const float2*)&bias[c];
                float v00 = lrelu(d[0] + bv.x), v01 = lrelu(d[1] + bv.y);
                float v10 = lrelu(d[2] + bv.x), v11 = lrelu(d[3] + bv.y);
                if (EPI == 0) {
                    float2 oA = {v00, v01}, oB = {v10, v11};
                    *(float2*)&Cf[(size_t)ra * ldc + c] = oA;
                    *(float2*)&Cf[(size_t)rb * ldc + c] = oB;
                } else {
                    __nv_bfloat16 h00, l00, h01, l01, h10, l10, h11, l11;
                    split_bf16(v00, h00, l00);
                    split_bf16(v01, h01, l01);
                    split_bf16(v10, h10, l10);
                    split_bf16(v11, h11, l11);
                    size_t pa = (EPI == 2) ? (oa + c) : ((size_t)ra * ldc + c);
                    size_t pb = (EPI == 2) ? (ob + c) : ((size_t)rb * ldc + c);
                    *(__nv_bfloat162*)&Ch[pa] = __nv_bfloat162(h00, h01);
                    *(__nv_bfloat162*)&Cl[pa] = __nv_bfloat162(l00, l01);
                    *(__nv_bfloat162*)&Ch[pb] = __nv_bfloat162(h10, h11);
                    *(__nv_bfloat162*)&Cl[pb] = __nv_bfloat162(l10, l11);
                }
            }
        }
    }
}

// ---------------- final layer ----------------
__global__ void k_out(const float* __restrict__ A, const float* __restrict__ Wo,
                      const float* __restrict__ bo, float* __restrict__ out)
{
    int b = blockIdx.x;
    int w = threadIdx.x >> 5, lane = threadIdx.x & 31;
    const float* a = A + (size_t)b * HID;
    float s = 0.f;
    for (int k = lane; k < HID; k += 32)
        s += a[k] * Wo[k * OUTD + w];
    #pragma unroll
    for (int o = 16; o > 0; o >>= 1) s += __shfl_xor_sync(0xFFFFFFFFu, s, o);
    __shared__ float sl[OUTD];
    if (lane == 0) sl[w] = s + bo[w];
    __syncthreads();
    if (threadIdx.x == 0) {
        float m = sl[0];
        #pragma unroll
        for (int o = 1; o < OUTD; o++) m = fmaxf(m, sl[o]);
        float sum = 0.f;
        #pragma unroll
        for (int o = 0; o < OUTD; o++) sum += expf(sl[o] - m);
        float l = logf(sum);
        #pragma unroll
        for (int o = 0; o < OUTD; o++) out[b * OUTD + o] = sl[o] - m - l;
    }
}

// ---------------- launch ----------------
static inline int cdiv(int a, int b) { return (a + b - 1) / b; }

extern "C" void kernel_launch(void* const* d_in, const int* in_sizes, int n_in,
                              void* d_out, int out_size)
{
    const float* x   = (const float*)d_in[0];
    const void*  ei  = d_in[1];
    const float* ew  = (const float*)d_in[2];
    const float* W1  = (const float*)d_in[3];
    const float* b1  = (const float*)d_in[4];
    const float* W2  = (const float*)d_in[5];
    const float* b2  = (const float*)d_in[6];
    const float* Wf0 = (const float*)d_in[7];
    const float* bf0 = (const float*)d_in[8];
    const float* Wf1 = (const float*)d_in[9];
    const float* bf1 = (const float*)d_in[10];
    const float* Wf2 = (const float*)d_in[11];
    const float* bf2 = (const float*)d_in[12];
    const float* Wo  = (const float*)d_in[13];
    const float* bo  = (const float*)d_in[14];
    float* out = (float*)d_out;

    __nv_bfloat16 *aggxh, *aggxl, *W1th, *W1tl, *W2th, *W2tl, *agg1h, *agg1l;
    __nv_bfloat16 *xcath, *xcatl, *Wf0th, *Wf0tl, *t0h, *t0l, *Wf1th, *Wf1tl;
    __nv_bfloat16 *t1h, *t1l, *Wf2th, *Wf2tl;
    float *h1, *t0f, *t2;
    cudaGetSymbolAddress((void**)&aggxh, g_aggx_h);
    cudaGetSymbolAddress((void**)&aggxl, g_aggx_l);
    cudaGetSymbolAddress((void**)&W1th,  g_W1t_h);
    cudaGetSymbolAddress((void**)&W1tl,  g_W1t_l);
    cudaGetSymbolAddress((void**)&W2th,  g_W2t_h);
    cudaGetSymbolAddress((void**)&W2tl,  g_W2t_l);
    cudaGetSymbolAddress((void**)&agg1h, g_agg1_h);
    cudaGetSymbolAddress((void**)&agg1l, g_agg1_l);
    cudaGetSymbolAddress((void**)&xcath, g_xcat_h);
    cudaGetSymbolAddress((void**)&xcatl, g_xcat_l);
    cudaGetSymbolAddress((void**)&Wf0th, g_Wf0t_h);
    cudaGetSymbolAddress((void**)&Wf0tl, g_Wf0t_l);
    cudaGetSymbolAddress((void**)&t0h,   g_t0_h);
    cudaGetSymbolAddress((void**)&t0l,   g_t0_l);
    cudaGetSymbolAddress((void**)&Wf1th, g_Wf1t_h);
    cudaGetSymbolAddress((void**)&Wf1tl, g_Wf1t_l);
    cudaGetSymbolAddress((void**)&t1h,   g_t1_h);
    cudaGetSymbolAddress((void**)&t1l,   g_t1_l);
    cudaGetSymbolAddress((void**)&Wf2th, g_Wf2t_h);
    cudaGetSymbolAddress((void**)&Wf2tl, g_Wf2t_l);
    cudaGetSymbolAddress((void**)&h1,    g_h1);
    cudaGetSymbolAddress((void**)&t0f,   g_t0f);
    cudaGetSymbolAddress((void**)&t2,    g_t2);

    const int SMEM = 2 * (int)BUFSZ;   // 147456
    cudaFuncSetAttribute(k_mma_gemm<0>, cudaFuncAttributeMaxDynamicSharedMemorySize, SMEM);
    cudaFuncSetAttribute(k_mma_gemm<1>, cudaFuncAttributeMaxDynamicSharedMemorySize, SMEM);
    cudaFuncSetAttribute(k_mma_gemm<2>, cudaFuncAttributeMaxDynamicSharedMemorySize, SMEM);
    cudaFuncSetAttribute(k_mma_gemm<3>, cudaFuncAttributeMaxDynamicSharedMemorySize, SMEM);

    const int TPB = 256;

    // graph normalization + CSR build
    k_detect<<<1, 1>>>((const int*)ei);
    k_init<<<cdiv(NN, TPB), TPB>>>();
    k_edges<<<cdiv(EE, TPB), TPB>>>(ei, ew);
    k_dis<<<cdiv(NN, TPB), TPB>>>();
    k_scan<<<1, 1024>>>();
    k_fill<<<cdiv(EE, TPB), TPB>>>(ew);

    // weight transposes + split conversion
    {
        dim3 blk(32, 8);
        k_wtrans<<<dim3(2, 16), blk>>>(W1, FEA, 64, W1th, W1tl);
        k_wtrans<<<dim3(16, 16), blk>>>(W2, HID, HID, W2th, W2tl);
        k_wtrans<<<dim3(KP0 / 32, 16), blk>>>(Wf0, FLAT, KP0, Wf0th, Wf0tl);
        k_wtrans<<<dim3(16, 16), blk>>>(Wf1, HID, HID, Wf1th, Wf1tl);
        k_wtrans<<<dim3(16, 16), blk>>>(Wf2, HID, HID, Wf2th, Wf2tl);
    }

    // conv1: gather (split-bf16) then mma GEMM -> h1 fp32
    k_gather1<<<NN, 64>>>(x);
    k_mma_gemm<0><<<dim3(4, 176, 1), 256, SMEM>>>(
        aggxh, aggxl, 64, W1th, W1tl, 64, b1, h1, nullptr, nullptr, HID, 1, 1);

    // conv2: gather h1 -> agg1 (split), GEMM scatters into xcat
    k_gather2<<<NN, 256>>>();
    k_copyx<<<cdiv(NN * FEA, TPB), TPB>>>(x);
    k_padxcat<<<cdiv(BGR * 24, TPB), TPB>>>();
    k_mma_gemm<2><<<dim3(4, 176, 1), 256, SMEM>>>(
        agg1h, agg1l, HID, W2th, W2tl, HID, b2, nullptr, xcath, xcatl, 0, 8, 8);

    // f0: split-K=8 with fp32 atomic reduce, then bias+lrelu+split
    k_zero_t0f<<<cdiv(BGR * HID, TPB), TPB>>>();
    k_mma_gemm<3><<<dim3(4, 8, 8), 256, SMEM>>>(
        xcath, xcatl, KP0, Wf0th, Wf0tl, KP0, nullptr, t0f, nullptr, nullptr, HID, NCH0, 25);
    k_fin_t0<<<cdiv(BGR * HID, TPB), TPB>>>(bf0);

    // f1, f2
    k_mma_gemm<1><<<dim3(4, 8, 1), 256, SMEM>>>(
        t0h, t0l, HID, Wf1th, Wf1tl, HID, bf1, nullptr, t1h, t1l, HID, 8, 8);
    k_mma_gemm<0><<<dim3(4, 8, 1), 256, SMEM>>>(
        t1h, t1l, HID, Wf2th, Wf2tl, HID, bf2, t2, nullptr, nullptr, HID, 8, 8);

    // output head + log_softmax
    k_out<<<BGR, 128>>>(t2, Wo, bo, out);
}

// round 6
// speedup vs baseline: 4.8980x; 1.0795x over previous
#include <cuda_runtime.h>
#include <cuda_bf16.h>
#include <cstdint>

#define NN   22528
#define EE   360448
#define FEA  60
#define HID  512
#define OUTD 4
#define MA   22
#define BGR  1024
#define CAT  572
#define FLAT 12584
#define KP0  12608
#define NCH0 197

// ---------------- device scratch ----------------
__device__ int   g_flag;
__device__ float g_deg[NN];
__device__ float g_dis[NN];
__device__ int   g_row[EE];
__device__ int   g_col[EE];
__device__ int   g_cnt[NN];
__device__ int   g_cur[NN];
__device__ int   g_off[NN + 1];
__device__ int   g_src[EE];
__device__ float g_w[EE];

__device__ __align__(16) __nv_bfloat16 g_aggx_h[(size_t)NN * 64];
__device__ __align__(16) __nv_bfloat16 g_aggx_l[(size_t)NN * 64];
__device__ __align__(16) __nv_bfloat16 g_W1t_h[512 * 64];
__device__ __align__(16) __nv_bfloat16 g_W1t_l[512 * 64];
__device__ __align__(16) float         g_h1[(size_t)NN * HID];
__device__ __align__(16) __nv_bfloat16 g_W2t_h[512 * 512];
__device__ __align__(16) __nv_bfloat16 g_W2t_l[512 * 512];
__device__ __align__(16) __nv_bfloat16 g_agg1_h[(size_t)NN * HID];
__device__ __align__(16) __nv_bfloat16 g_agg1_l[(size_t)NN * HID];
__device__ __align__(16) __nv_bfloat16 g_xcat_h[(size_t)BGR * KP0];
__device__ __align__(16) __nv_bfloat16 g_xcat_l[(size_t)BGR * KP0];
__device__ __align__(16) __nv_bfloat16 g_Wf0t_h[(size_t)512 * KP0];
__device__ __align__(16) __nv_bfloat16 g_Wf0t_l[(size_t)512 * KP0];
__device__ __align__(16) float         g_t0f[BGR * HID];
__device__ __align__(16) __nv_bfloat16 g_t0_h[BGR * HID];
__device__ __align__(16) __nv_bfloat16 g_t0_l[BGR * HID];
__device__ __align__(16) __nv_bfloat16 g_Wf1t_h[512 * 512];
__device__ __align__(16) __nv_bfloat16 g_Wf1t_l[512 * 512];
__device__ __align__(16) __nv_bfloat16 g_t1_h[BGR * HID];
__device__ __align__(16) __nv_bfloat16 g_t1_l[BGR * HID];
__device__ __align__(16) __nv_bfloat16 g_Wf2t_h[512 * 512];
__device__ __align__(16) __nv_bfloat16 g_Wf2t_l[512 * 512];
__device__ __align__(16) float         g_t2[BGR * HID];

// ---------------- helpers ----------------
__device__ __forceinline__ uint32_t smem_u32(const void* p) {
    uint32_t a;
    asm("{ .reg .u64 t; cvta.to.shared.u64 t, %1; cvt.u32.u64 %0, t; }" : "=r"(a) : "l"(p));
    return a;
}
__device__ __forceinline__ void ldsm4(uint32_t* r, uint32_t addr) {
    asm volatile("ldmatrix.sync.aligned.m8n8.x4.shared.b16 {%0,%1,%2,%3}, [%4];"
        : "=r"(r[0]), "=r"(r[1]), "=r"(r[2]), "=r"(r[3]) : "r"(addr));
}
__device__ __forceinline__ void mma16816(float* d, const uint32_t* a, uint32_t b0, uint32_t b1) {
    asm volatile("mma.sync.aligned.m16n8k16.row.col.f32.bf16.bf16.f32 "
        "{%0,%1,%2,%3}, {%4,%5,%6,%7}, {%8,%9}, {%0,%1,%2,%3};"
        : "+f"(d[0]), "+f"(d[1]), "+f"(d[2]), "+f"(d[3])
        : "r"(a[0]), "r"(a[1]), "r"(a[2]), "r"(a[3]), "r"(b0), "r"(b1));
}
#define CP16(d, s)   asm volatile("cp.async.cg.shared.global [%0], [%1], 16;" :: "r"(d), "l"(s))
#define CP_COMMIT()  asm volatile("cp.async.commit_group;" ::: "memory")
#define CP_WAIT0()   asm volatile("cp.async.wait_group 0;" ::: "memory")
#define CP_WAIT1()   asm volatile("cp.async.wait_group 1;" ::: "memory")

__device__ __forceinline__ float lrelu(float v) { return v > 0.f ? v : 0.01f * v; }
__device__ __forceinline__ void split_bf16(float v, __nv_bfloat16& h, __nv_bfloat16& l) {
    h = __float2bfloat16(v);
    l = __float2bfloat16(v - __bfloat162float(h));
}

// ---------------- setup ----------------
__global__ void k_setup(const int* ei) {
    int i = blockIdx.x * blockDim.x + threadIdx.x;
    if (i < NN) { g_deg[i] = 1.0f; g_cnt[i] = 0; g_cur[i] = 0; }
    if (i == 0) {
        int f = 1;
        for (int j = 0; j < 64; j++)
            if (ei[2 * j + 1] != 0) { f = 0; break; }
        g_flag = f;
    }
}
__global__ void k_edges(const void* ei, const float* __restrict__ ew) {
    int e = blockIdx.x * blockDim.x + threadIdx.x;
    if (e >= EE) return;
    int r, c;
    if (g_flag) {
        const long long* p = (const long long*)ei;
        r = (int)p[e]; c = (int)p[EE + e];
    } else {
        const int* p = (const int*)ei;
        r = p[e]; c = p[EE + e];
    }
    g_row[e] = r; g_col[e] = c;
    atomicAdd(&g_deg[c], ew[e]);
    atomicAdd(&g_cnt[c], 1);
}
// fused: exclusive scan of cnt -> off, plus dis = rsqrt(deg)
__global__ void k_scan_dis() {
    __shared__ int sh[1024];
    int t = threadIdx.x;
    int base = t * 22;
    int local[22];
    int s = 0;
    #pragma unroll
    for (int i = 0; i < 22; i++) {
        local[i] = g_cnt[base + i];
        s += local[i];
        float d = g_deg[base + i];
        g_dis[base + i] = (d > 0.f) ? rsqrtf(d) : 0.f;
    }
    sh[t] = s;
    __syncthreads();
    for (int off = 1; off < 1024; off <<= 1) {
        int v = (t >= off) ? sh[t - off] : 0;
        __syncthreads();
        sh[t] += v;
        __syncthreads();
    }
    int pre = (t == 0) ? 0 : sh[t - 1];
    #pragma unroll
    for (int i = 0; i < 22; i++) { g_off[base + i] = pre; pre += local[i]; }
    if (t == 0) g_off[NN] = EE;
}
__global__ void k_fill(const float* __restrict__ ew) {
    int e = blockIdx.x * blockDim.x + threadIdx.x;
    if (e >= EE) return;
    int r = g_row[e], c = g_col[e];
    int p = g_off[c] + atomicAdd(&g_cur[c], 1);
    g_src[p] = r;
    g_w[p] = g_dis[r] * ew[e] * g_dis[c];
}

// ---------------- CSR gathers ----------------
__global__ void k_gather1(const float* __restrict__ x) {
    int n = blockIdx.x;
    int f = threadIdx.x;               // 64
    float d = g_dis[n];
    float acc = 0.f;
    if (f < FEA) acc = d * d * x[(size_t)n * FEA + f];
    int s = g_off[n], e = g_off[n + 1];
    for (int p = s; p < e; p++) {
        int src = g_src[p];
        float w = g_w[p];
        if (f < FEA) acc += x[(size_t)src * FEA + f] * w;
    }
    if (f >= FEA) acc = 0.f;
    __nv_bfloat16 h, l;
    split_bf16(acc, h, l);
    g_aggx_h[(size_t)n * 64 + f] = h;
    g_aggx_l[(size_t)n * 64 + f] = l;
}

__global__ void k_gather2() {
    int n = blockIdx.x;
    int f4 = threadIdx.x;              // 128 threads, float4 each
    float d = g_dis[n];
    float s2 = d * d;
    float4 acc = ((const float4*)(g_h1 + (size_t)n * HID))[f4];
    acc.x *= s2; acc.y *= s2; acc.z *= s2; acc.w *= s2;
    int s = g_off[n], e = g_off[n + 1];
    for (int p = s; p < e; p++) {
        int src = g_src[p];
        float w = g_w[p];
        float4 v = ((const float4*)(g_h1 + (size_t)src * HID))[f4];
        acc.x += v.x * w; acc.y += v.y * w;
        acc.z += v.z * w; acc.w += v.w * w;
    }
    __nv_bfloat16 h0, l0, h1b, l1, h2, l2, h3, l3;
    split_bf16(acc.x, h0, l0);
    split_bf16(acc.y, h1b, l1);
    split_bf16(acc.z, h2, l2);
    split_bf16(acc.w, h3, l3);
    size_t o = (size_t)n * HID + f4 * 4;
    *(__nv_bfloat162*)&g_agg1_h[o]     = __nv_bfloat162(h0, h1b);
    *(__nv_bfloat162*)&g_agg1_h[o + 2] = __nv_bfloat162(h2, h3);
    *(__nv_bfloat162*)&g_agg1_l[o]     = __nv_bfloat162(l0, l1);
    *(__nv_bfloat162*)&g_agg1_l[o + 2] = __nv_bfloat162(l2, l3);
}

// ---------------- weight transpose + split ----------------
__global__ void k_wtrans(const float* __restrict__ W, int K, int Kpad,
                         __nv_bfloat16* __restrict__ oh, __nv_bfloat16* __restrict__ ol) {
    __shared__ float tile[32][33];
    int kb = blockIdx.x * 32, nb = blockIdx.y * 32;
    int tx = threadIdx.x, ty = threadIdx.y;   // 32 x 8
    #pragma unroll
    for (int i = 0; i < 4; i++) {
        int row = kb + ty + i * 8;
        tile[ty + i * 8][tx] = (row < K) ? W[(size_t)row * 512 + nb + tx] : 0.f;
    }
    __syncthreads();
    #pragma unroll
    for (int i = 0; i < 4; i++) {
        int n = nb + ty + i * 8;
        int k = kb + tx;
        float v = tile[tx][ty + i * 8];
        __nv_bfloat16 h, l;
        split_bf16(v, h, l);
        oh[(size_t)n * Kpad + k] = h;
        ol[(size_t)n * Kpad + k] = l;
    }
}
// 3 square 512x512 transposes in one launch (z selects matrix)
__global__ void k_wtrans3(const float* __restrict__ Wa, const float* __restrict__ Wb,
                          const float* __restrict__ Wc,
                          __nv_bfloat16* __restrict__ oha, __nv_bfloat16* __restrict__ ola,
                          __nv_bfloat16* __restrict__ ohb, __nv_bfloat16* __restrict__ olb,
                          __nv_bfloat16* __restrict__ ohc, __nv_bfloat16* __restrict__ olc) {
    __shared__ float tile[32][33];
    const float* W = (blockIdx.z == 0) ? Wa : (blockIdx.z == 1) ? Wb : Wc;
    __nv_bfloat16* oh = (blockIdx.z == 0) ? oha : (blockIdx.z == 1) ? ohb : ohc;
    __nv_bfloat16* ol = (blockIdx.z == 0) ? ola : (blockIdx.z == 1) ? olb : olc;
    int kb = blockIdx.x * 32, nb = blockIdx.y * 32;
    int tx = threadIdx.x, ty = threadIdx.y;
    #pragma unroll
    for (int i = 0; i < 4; i++)
        tile[ty + i * 8][tx] = W[(size_t)(kb + ty + i * 8) * 512 + nb + tx];
    __syncthreads();
    #pragma unroll
    for (int i = 0; i < 4; i++) {
        int n = nb + ty + i * 8;
        int k = kb + tx;
        float v = tile[tx][ty + i * 8];
        __nv_bfloat16 h, l;
        split_bf16(v, h, l);
        oh[(size_t)n * 512 + k] = h;
        ol[(size_t)n * 512 + k] = l;
    }
}

// copy raw x into xcat (split) + zero pad cols, one kernel
__global__ void k_copyx(const float* __restrict__ x) {
    int t = blockIdx.x * blockDim.x + threadIdx.x;
    if (t < NN * FEA) {
        int n = t / FEA, f = t - n * FEA;
        int b = n / MA, j = n - b * MA;
        size_t o = (size_t)b * KP0 + j * CAT + HID + f;
        __nv_bfloat16 h, l;
        split_bf16(x[t], h, l);
        g_xcat_h[o] = h;
        g_xcat_l[o] = l;
    } else if (t < NN * FEA + BGR * 24) {
        int t2 = t - NN * FEA;
        int b = t2 / 24, f = t2 - b * 24;
        size_t o = (size_t)b * KP0 + FLAT + f;
        g_xcat_h[o] = __float2bfloat16(0.f);
        g_xcat_l[o] = __float2bfloat16(0.f);
    }
}
__global__ void k_zero_t0f() {
    int t = blockIdx.x * blockDim.x + threadIdx.x;
    if (t < BGR * HID) g_t0f[t] = 0.f;
}
__global__ void k_fin_t0(const float* __restrict__ bias) {
    int t = blockIdx.x * blockDim.x + threadIdx.x;
    if (t >= BGR * HID) return;
    int c = t & 511;
    float v = lrelu(g_t0f[t] + bias[c]);
    __nv_bfloat16 h, l;
    split_bf16(v, h, l);
    g_t0_h[t] = h;
    g_t0_l[t] = l;
}

// ================= 128x128 mma GEMM, 3-stage cp.async =================
// EPI: 0 fp32+bias+lrelu, 2 xcat-scatter, 3 atomicAdd raw.
#define OFF_AL 18432u
#define OFF_BH 36864u
#define OFF_BL 55296u
#define BUFSZ  73728u

template <int EPI>
__global__ void __launch_bounds__(256, 1)
k_mma_gemm(const __nv_bfloat16* __restrict__ Ah, const __nv_bfloat16* __restrict__ Al, int lda,
           const __nv_bfloat16* __restrict__ Bh, const __nv_bfloat16* __restrict__ Bl, int ldb,
           const float* __restrict__ bias,
           float* __restrict__ Cf, __nv_bfloat16* __restrict__ Ch, __nv_bfloat16* __restrict__ Cl,
           int ldc, int nch, int cper)
{
    extern __shared__ char smx[];
    const uint32_t smb = smem_u32(smx);
    const int tid = threadIdx.x;
    const int wid = tid >> 5, lane = tid & 31;
    const int wm = wid & 1, wn = wid >> 1;
    const int row0 = blockIdx.y * 128, col0 = blockIdx.x * 128;
    const int c0 = blockIdx.z * cper;
    const int nc = min(nch, c0 + cper) - c0;

    const __nv_bfloat16* pAh = Ah + (size_t)row0 * lda;
    const __nv_bfloat16* pAl = Al + (size_t)row0 * lda;
    const __nv_bfloat16* pBh = Bh + (size_t)col0 * ldb;
    const __nv_bfloat16* pBl = Bl + (size_t)col0 * ldb;

    auto fill = [&](int b, int c) {
        const int kb = c * 64;
        uint32_t base = smb + b * BUFSZ;
        #pragma unroll
        for (int i = 0; i < 4; i++) {
            int idx = i * 256 + tid;
            int row = idx >> 3, seg = idx & 7;
            uint32_t d = base + (uint32_t)(row * 144 + seg * 16);
            size_t sa = (size_t)row * lda + kb + seg * 8;
            size_t sb = (size_t)row * ldb + kb + seg * 8;
            CP16(d,          pAh + sa);
            CP16(d + OFF_AL, pAl + sa);
            CP16(d + OFF_BH, pBh + sb);
            CP16(d + OFF_BL, pBl + sb);
        }
    };

    float acc[4][4][4];
    #pragma unroll
    for (int i = 0; i < 4; i++)
        #pragma unroll
        for (int j = 0; j < 4; j++)
            #pragma unroll
            for (int q = 0; q < 4; q++) acc[i][j][q] = 0.f;

    const int g2 = lane >> 3, rr = lane & 7;
    const uint32_t aoff = (uint32_t)((wm * 64 + (g2 & 1) * 8 + rr) * 144 + (g2 >> 1) * 16);
    const uint32_t boff = (uint32_t)((wn * 32 + (g2 >> 1) * 8 + rr) * 144 + (g2 & 1) * 16);

    fill(0, c0);
    CP_COMMIT();
    if (nc > 1) { fill(1, c0 + 1); CP_COMMIT(); }

    for (int ci = 0; ci < nc; ci++) {
        if (ci + 1 < nc) CP_WAIT1(); else CP_WAIT0();
        __syncthreads();
        if (ci + 2 < nc) { fill((ci + 2) % 3, c0 + ci + 2); CP_COMMIT(); }
        uint32_t base = smb + (uint32_t)(ci % 3) * BUFSZ;
        #pragma unroll
        for (int k16 = 0; k16 < 4; k16++) {
            uint32_t Af[4][4], Lf[4][4], Bf[2][4], Mf[2][4];
            #pragma unroll
            for (int mt = 0; mt < 4; mt++) {
                ldsm4(Af[mt], base + aoff + mt * 2304 + k16 * 32);
                ldsm4(Lf[mt], base + OFF_AL + aoff + mt * 2304 + k16 * 32);
            }
            #pragma unroll
            for (int nt2 = 0; nt2 < 2; nt2++) {
                ldsm4(Bf[nt2], base + OFF_BH + boff + nt2 * 2304 + k16 * 32);
                ldsm4(Mf[nt2], base + OFF_BL + boff + nt2 * 2304 + k16 * 32);
            }
            #pragma unroll
            for (int mt = 0; mt < 4; mt++)
                #pragma unroll
                for (int nt = 0; nt < 4; nt++) {
                    uint32_t bh0 = Bf[nt >> 1][(nt & 1) * 2], bh1 = Bf[nt >> 1][(nt & 1) * 2 + 1];
                    uint32_t bl0 = Mf[nt >> 1][(nt & 1) * 2], bl1 = Mf[nt >> 1][(nt & 1) * 2 + 1];
                    mma16816(acc[mt][nt], Af[mt], bh0, bh1);
                    mma16816(acc[mt][nt], Af[mt], bl0, bl1);
                    mma16816(acc[mt][nt], Lf[mt], bh0, bh1);
                }
        }
        __syncthreads();
    }

    // epilogue
    const int g = lane >> 2, t = lane & 3;
    #pragma unroll
    for (int mt = 0; mt < 4; mt++) {
        const int ra = row0 + wm * 64 + mt * 16 + g;
        const int rb = ra + 8;
        size_t oa = 0, ob = 0;
        if (EPI == 2) {
            int bg = ra / MA, j = ra - bg * MA;
            oa = (size_t)bg * KP0 + (size_t)j * CAT;
            bg = rb / MA; j = rb - bg * MA;
            ob = (size_t)bg * KP0 + (size_t)j * CAT;
        }
        #pragma unroll
        for (int nt = 0; nt < 4; nt++) {
            const int c = col0 + wn * 32 + nt * 8 + t * 2;
            float* d = acc[mt][nt];
            if (EPI == 3) {
                atomicAdd(&Cf[(size_t)ra * ldc + c],     d[0]);
                atomicAdd(&Cf[(size_t)ra * ldc + c + 1], d[1]);
                atomicAdd(&Cf[(size_t)rb * ldc + c],     d[2]);
                atomicAdd(&Cf[(size_t)rb * ldc + c + 1], d[3]);
            } else {
                float2 bv = *(const float2*)&bias[c];
                float v00 = lrelu(d[0] + bv.x), v01 = lrelu(d[1] + bv.y);
                float v10 = lrelu(d[2] + bv.x), v11 = lrelu(d[3] + bv.y);
                if (EPI == 0) {
                    float2 oA = {v00, v01}, oB = {v10, v11};
                    *(float2*)&Cf[(size_t)ra * ldc + c] = oA;
                    *(float2*)&Cf[(size_t)rb * ldc + c] = oB;
                } else {
                    __nv_bfloat16 h00, l00, h01, l01, h10, l10, h11, l11;
                    split_bf16(v00, h00, l00);
                    split_bf16(v01, h01, l01);
                    split_bf16(v10, h10, l10);
                    split_bf16(v11, h11, l11);
                    *(__nv_bfloat162*)&Ch[oa + c] = __nv_bfloat162(h00, h01);
                    *(__nv_bfloat162*)&Cl[oa + c] = __nv_bfloat162(l00, l01);
                    *(__nv_bfloat162*)&Ch[ob + c] = __nv_bfloat162(h10, h11);
                    *(__nv_bfloat162*)&Cl[ob + c] = __nv_bfloat162(l10, l11);
                }
            }
        }
    }
}

// ================= 64x64 mma GEMM (f1/f2), 3-stage, 4 warps =================
// EPI: 0 fp32 store, 1 bf16 hi/lo store. Both bias+lrelu.
#define B64_AL 9216u
#define B64_BH 18432u
#define B64_BL 27648u
#define BUF64  36864u

template <int EPI>
__global__ void __launch_bounds__(128, 2)
k_mma64(const __nv_bfloat16* __restrict__ Ah, const __nv_bfloat16* __restrict__ Al, int lda,
        const __nv_bfloat16* __restrict__ Bh, const __nv_bfloat16* __restrict__ Bl, int ldb,
        const float* __restrict__ bias,
        float* __restrict__ Cf, __nv_bfloat16* __restrict__ Ch, __nv_bfloat16* __restrict__ Cl,
        int ldc, int nc)
{
    extern __shared__ char smx[];
    const uint32_t smb = smem_u32(smx);
    const int tid = threadIdx.x;
    const int wid = tid >> 5, lane = tid & 31;
    const int wm = wid & 1, wn = wid >> 1;
    const int row0 = blockIdx.y * 64, col0 = blockIdx.x * 64;

    const __nv_bfloat16* pAh = Ah + (size_t)row0 * lda;
    const __nv_bfloat16* pAl = Al + (size_t)row0 * lda;
    const __nv_bfloat16* pBh = Bh + (size_t)col0 * ldb;
    const __nv_bfloat16* pBl = Bl + (size_t)col0 * ldb;

    auto fill = [&](int b, int c) {
        const int kb = c * 64;
        uint32_t base = smb + b * BUF64;
        #pragma unroll
        for (int i = 0; i < 4; i++) {
            int idx = i * 128 + tid;
            int row = idx >> 3, seg = idx & 7;
            uint32_t d = base + (uint32_t)(row * 144 + seg * 16);
            size_t sa = (size_t)row * lda + kb + seg * 8;
            size_t sb = (size_t)row * ldb + kb + seg * 8;
            CP16(d,          pAh + sa);
            CP16(d + B64_AL, pAl + sa);
            CP16(d + B64_BH, pBh + sb);
            CP16(d + B64_BL, pBl + sb);
        }
    };

    float acc[2][4][4];
    #pragma unroll
    for (int i = 0; i < 2; i++)
        #pragma unroll
        for (int j = 0; j < 4; j++)
            #pragma unroll
            for (int q = 0; q < 4; q++) acc[i][j][q] = 0.f;

    const int g2 = lane >> 3, rr = lane & 7;
    const uint32_t aoff = (uint32_t)((wm * 32 + (g2 & 1) * 8 + rr) * 144 + (g2 >> 1) * 16);
    const uint32_t boff = (uint32_t)((wn * 32 + (g2 >> 1) * 8 + rr) * 144 + (g2 & 1) * 16);

    fill(0, 0);
    CP_COMMIT();
    if (nc > 1) { fill(1, 1); CP_COMMIT(); }

    for (int ci = 0; ci < nc; ci++) {
        if (ci + 1 < nc) CP_WAIT1(); else CP_WAIT0();
        __syncthreads();
        if (ci + 2 < nc) { fill((ci + 2) % 3, ci + 2); CP_COMMIT(); }
        uint32_t base = smb + (uint32_t)(ci % 3) * BUF64;
        #pragma unroll
        for (int k16 = 0; k16 < 4; k16++) {
            uint32_t Af[2][4], Lf[2][4], Bf[2][4], Mf[2][4];
            #pragma unroll
            for (int mt = 0; mt < 2; mt++) {
                ldsm4(Af[mt], base + aoff + mt * 2304 + k16 * 32);
                ldsm4(Lf[mt], base + B64_AL + aoff + mt * 2304 + k16 * 32);
            }
            #pragma unroll
            for (int nt2 = 0; nt2 < 2; nt2++) {
                ldsm4(Bf[nt2], base + B64_BH + boff + nt2 * 2304 + k16 * 32);
                ldsm4(Mf[nt2], base + B64_BL + boff + nt2 * 2304 + k16 * 32);
            }
            #pragma unroll
            for (int mt = 0; mt < 2; mt++)
                #pragma unroll
                for (int nt = 0; nt < 4; nt++) {
                    uint32_t bh0 = Bf[nt >> 1][(nt & 1) * 2], bh1 = Bf[nt >> 1][(nt & 1) * 2 + 1];
                    uint32_t bl0 = Mf[nt >> 1][(nt & 1) * 2], bl1 = Mf[nt >> 1][(nt & 1) * 2 + 1];
                    mma16816(acc[mt][nt], Af[mt], bh0, bh1);
                    mma16816(acc[mt][nt], Af[mt], bl0, bl1);
                    mma16816(acc[mt][nt], Lf[mt], bh0, bh1);
                }
        }
        __syncthreads();
    }

    const int g = lane >> 2, t = lane & 3;
    #pragma unroll
    for (int mt = 0; mt < 2; mt++) {
        const int ra = row0 + wm * 32 + mt * 16 + g;
        const int rb = ra + 8;
        #pragma unroll
        for (int nt = 0; nt < 4; nt++) {
            const int c = col0 + wn * 32 + nt * 8 + t * 2;
            float* d = acc[mt][nt];
            float2 bv = *(const float2*)&bias[c];
            float v00 = lrelu(d[0] + bv.x), v01 = lrelu(d[1] + bv.y);
            float v10 = lrelu(d[2] + bv.x), v11 = lrelu(d[3] + bv.y);
            if (EPI == 0) {
                float2 oA = {v00, v01}, oB = {v10, v11};
                *(float2*)&Cf[(size_t)ra * ldc + c] = oA;
                *(float2*)&Cf[(size_t)rb * ldc + c] = oB;
            } else {
                __nv_bfloat16 h00, l00, h01, l01, h10, l10, h11, l11;
                split_bf16(v00, h00, l00);
                split_bf16(v01, h01, l01);
                split_bf16(v10, h10, l10);
                split_bf16(v11, h11, l11);
                *(__nv_bfloat162*)&Ch[(size_t)ra * ldc + c] = __nv_bfloat162(h00, h01);
                *(__nv_bfloat162*)&Cl[(size_t)ra * ldc + c] = __nv_bfloat162(l00, l01);
                *(__nv_bfloat162*)&Ch[(size_t)rb * ldc + c] = __nv_bfloat162(h10, h11);
                *(__nv_bfloat162*)&Cl[(size_t)rb * ldc + c] = __nv_bfloat162(l10, l11);
            }
        }
    }
}

// ---------------- final layer ----------------
__global__ void k_out(const float* __restrict__ A, const float* __restrict__ Wo,
                      const float* __restrict__ bo, float* __restrict__ out)
{
    int b = blockIdx.x;
    int w = threadIdx.x >> 5, lane = threadIdx.x & 31;
    const float* a = A + (size_t)b * HID;
    float s = 0.f;
    for (int k = lane; k < HID; k += 32)
        s += a[k] * Wo[k * OUTD + w];
    #pragma unroll
    for (int o = 16; o > 0; o >>= 1) s += __shfl_xor_sync(0xFFFFFFFFu, s, o);
    __shared__ float sl[OUTD];
    if (lane == 0) sl[w] = s + bo[w];
    __syncthreads();
    if (threadIdx.x == 0) {
        float m = sl[0];
        #pragma unroll
        for (int o = 1; o < OUTD; o++) m = fmaxf(m, sl[o]);
        float sum = 0.f;
        #pragma unroll
        for (int o = 0; o < OUTD; o++) sum += expf(sl[o] - m);
        float l = logf(sum);
        #pragma unroll
        for (int o = 0; o < OUTD; o++) out[b * OUTD + o] = sl[o] - m - l;
    }
}

// ---------------- launch ----------------
static inline int cdiv(int a, int b) { return (a + b - 1) / b; }

extern "C" void kernel_launch(void* const* d_in, const int* in_sizes, int n_in,
                              void* d_out, int out_size)
{
    const float* x   = (const float*)d_in[0];
    const void*  ei  = d_in[1];
    const float* ew  = (const float*)d_in[2];
    const float* W1  = (const float*)d_in[3];
    const float* b1  = (const float*)d_in[4];
    const float* W2  = (const float*)d_in[5];
    const float* b2  = (const float*)d_in[6];
    const float* Wf0 = (const float*)d_in[7];
    const float* bf0 = (const float*)d_in[8];
    const float* Wf1 = (const float*)d_in[9];
    const float* bf1 = (const float*)d_in[10];
    const float* Wf2 = (const float*)d_in[11];
    const float* bf2 = (const float*)d_in[12];
    const float* Wo  = (const float*)d_in[13];
    const float* bo  = (const float*)d_in[14];
    float* out = (float*)d_out;

    __nv_bfloat16 *aggxh, *aggxl, *W1th, *W1tl, *W2th, *W2tl, *agg1h, *agg1l;
    __nv_bfloat16 *xcath, *xcatl, *Wf0th, *Wf0tl, *t0h, *t0l, *Wf1th, *Wf1tl;
    __nv_bfloat16 *t1h, *t1l, *Wf2th, *Wf2tl;
    float *h1, *t0f, *t2;
    cudaGetSymbolAddress((void**)&aggxh, g_aggx_h);
    cudaGetSymbolAddress((void**)&aggxl, g_aggx_l);
    cudaGetSymbolAddress((void**)&W1th,  g_W1t_h);
    cudaGetSymbolAddress((void**)&W1tl,  g_W1t_l);
    cudaGetSymbolAddress((void**)&W2th,  g_W2t_h);
    cudaGetSymbolAddress((void**)&W2tl,  g_W2t_l);
    cudaGetSymbolAddress((void**)&agg1h, g_agg1_h);
    cudaGetSymbolAddress((void**)&agg1l, g_agg1_l);
    cudaGetSymbolAddress((void**)&xcath, g_xcat_h);
    cudaGetSymbolAddress((void**)&xcatl, g_xcat_l);
    cudaGetSymbolAddress((void**)&Wf0th, g_Wf0t_h);
    cudaGetSymbolAddress((void**)&Wf0tl, g_Wf0t_l);
    cudaGetSymbolAddress((void**)&t0h,   g_t0_h);
    cudaGetSymbolAddress((void**)&t0l,   g_t0_l);
    cudaGetSymbolAddress((void**)&Wf1th, g_Wf1t_h);
    cudaGetSymbolAddress((void**)&Wf1tl, g_Wf1t_l);
    cudaGetSymbolAddress((void**)&t1h,   g_t1_h);
    cudaGetSymbolAddress((void**)&t1l,   g_t1_l);
    cudaGetSymbolAddress((void**)&Wf2th, g_Wf2t_h);
    cudaGetSymbolAddress((void**)&Wf2tl, g_Wf2t_l);
    cudaGetSymbolAddress((void**)&h1,    g_h1);
    cudaGetSymbolAddress((void**)&t0f,   g_t0f);
    cudaGetSymbolAddress((void**)&t2,    g_t2);

    const int SMEM  = 3 * (int)BUFSZ;   // 221184
    const int SMEM64 = 3 * (int)BUF64;  // 110592
    cudaFuncSetAttribute(k_mma_gemm<0>, cudaFuncAttributeMaxDynamicSharedMemorySize, SMEM);
    cudaFuncSetAttribute(k_mma_gemm<2>, cudaFuncAttributeMaxDynamicSharedMemorySize, SMEM);
    cudaFuncSetAttribute(k_mma_gemm<3>, cudaFuncAttributeMaxDynamicSharedMemorySize, SMEM);
    cudaFuncSetAttribute(k_mma64<0>, cudaFuncAttributeMaxDynamicSharedMemorySize, SMEM64);
    cudaFuncSetAttribute(k_mma64<1>, cudaFuncAttributeMaxDynamicSharedMemorySize, SMEM64);

    const int TPB = 256;

    // graph normalization + CSR build
    k_setup<<<cdiv(NN, TPB), TPB>>>((const int*)ei);
    k_edges<<<cdiv(EE, TPB), TPB>>>(ei, ew);
    k_scan_dis<<<1, 1024>>>();
    k_fill<<<cdiv(EE, TPB), TPB>>>(ew);

    // weight transposes + split conversion
    {
        dim3 blk(32, 8);
        k_wtrans<<<dim3(2, 16), blk>>>(W1, FEA, 64, W1th, W1tl);
        k_wtrans<<<dim3(KP0 / 32, 16), blk>>>(Wf0, FLAT, KP0, Wf0th, Wf0tl);
        k_wtrans3<<<dim3(16, 16, 3), blk>>>(W2, Wf1, Wf2,
                                            W2th, W2tl, Wf1th, Wf1tl, Wf2th, Wf2tl);
    }
    k_zero_t0f<<<cdiv(BGR * HID, TPB), TPB>>>();

    // conv1
    k_gather1<<<NN, 64>>>(x);
    k_mma_gemm<0><<<dim3(4, 176, 1), 256, SMEM>>>(
        aggxh, aggxl, 64, W1th, W1tl, 64, b1, h1, nullptr, nullptr, HID, 1, 1);

    // conv2 (epilogue scatters into xcat layout)
    k_gather2<<<NN, 128>>>();
    k_copyx<<<cdiv(NN * FEA + BGR * 24, TPB), TPB>>>(x);
    k_mma_gemm<2><<<dim3(4, 176, 1), 256, SMEM>>>(
        agg1h, agg1l, HID, W2th, W2tl, HID, b2, nullptr, xcath, xcatl, 0, 8, 8);

    // f0: split-K=8 with fp32 atomic reduce, then bias+lrelu+split
    k_mma_gemm<3><<<dim3(4, 8, 8), 256, SMEM>>>(
        xcath, xcatl, KP0, Wf0th, Wf0tl, KP0, nullptr, t0f, nullptr, nullptr, HID, NCH0, 25);
    k_fin_t0<<<cdiv(BGR * HID, TPB), TPB>>>(bf0);

    // f1, f2: 64x64 tiles, 128 CTAs each, direct epilogues
    k_mma64<1><<<dim3(8, 16), 128, SMEM64>>>(
        t0h, t0l, HID, Wf1th, Wf1tl, HID, bf1, nullptr, t1h, t1l, HID, 8);
    k_mma64<0><<<dim3(8, 16), 128, SMEM64>>>(
        t1h, t1l, HID, Wf2th, Wf2tl, HID, bf2, t2, nullptr, nullptr, HID, 8);

    // output head + log_softmax
    k_out<<<BGR, 128>>>(t2, Wo, bo, out);
}